// round 9
// baseline (speedup 1.0000x reference)
#include <cuda_runtime.h>
#include <cuda_bf16.h>

#define NB 8
#define NS 1024
#define ND 128
#define NROWS (NB*NS)   // 8192
#define BSD (NB*NS*ND)  // 1048576

#define NC 16           // coarse chunks (GEMM splits)
#define LC 64           // steps per coarse chunk
#define LF 16           // steps per fine sub-chunk (replay granularity)
#define UG 8            // prefetch group size (pass1)
#define NGRP (LC/UG)

#define KP 72           // padded bf16 k-stride in smem (conflict-free frag loads)

// ---- scratch (static device globals; no runtime allocation) ----
__device__ float  g_k[NROWS*ND];
__device__ float  g_v[NROWS*ND];
__device__ float  g_q[NROWS*ND];
__device__ float4 g_g4[NROWS];           // (om=1-a, e, th, 0) per (b,t)
__device__ float  g_dmap[6*NB*NC*ND];    // composed coarse diag maps
__device__ float  g_wmap[3*NB*NC];
__device__ float  g_part[NB*2*NC*ND*ND];

// ---- mma.sync m16n8k16 bf16 -> f32 ----
__device__ __forceinline__ void mma16816(float* c, const unsigned* a, const unsigned* b)
{
    asm volatile(
        "mma.sync.aligned.m16n8k16.row.col.f32.bf16.bf16.f32 "
        "{%0,%1,%2,%3}, {%4,%5,%6,%7}, {%8,%9}, {%0,%1,%2,%3};"
        : "+f"(c[0]), "+f"(c[1]), "+f"(c[2]), "+f"(c[3])
        : "r"(a[0]), "r"(a[1]), "r"(a[2]), "r"(a[3]), "r"(b[0]), "r"(b[1]));
}

__device__ __forceinline__ void bf16split(float f, __nv_bfloat16& h, __nv_bfloat16& l)
{
    h = __float2bfloat16_rn(f);
    l = __float2bfloat16_rn(f - __bfloat162float(h));
}

// ============================================================
// Kernel 1: y<3: k/v/q = x@W via bf16-split tensor mma; y==3: gates
// ============================================================
__global__ __launch_bounds__(256) void k1_qkv_gates(
    const float* __restrict__ x, const float* __restrict__ Wk,
    const float* __restrict__ Wv, const float* __restrict__ Wq,
    const float* __restrict__ Wg, const float* __restrict__ bg)
{
    const int which = blockIdx.y;
    if (which == 3) {
        const int base = blockIdx.x * 128;
        const int w = threadIdx.x >> 5, lane = threadIdx.x & 31;
        const float b0 = bg[0], b1 = bg[1], b2 = bg[2];
        const float w0a = Wg[lane*3+0],      w0b = Wg[lane*3+1],      w0c = Wg[lane*3+2];
        const float w1a = Wg[(lane+32)*3+0], w1b = Wg[(lane+32)*3+1], w1c = Wg[(lane+32)*3+2];
        const float w2a = Wg[(lane+64)*3+0], w2b = Wg[(lane+64)*3+1], w2c = Wg[(lane+64)*3+2];
        const float w3a = Wg[(lane+96)*3+0], w3b = Wg[(lane+96)*3+1], w3c = Wg[(lane+96)*3+2];
        for (int rr = 0; rr < 16; rr++) {
            const int r = base + w*16 + rr;
            const float* __restrict__ xr = x + r * ND;
            float x0 = xr[lane], x1 = xr[lane+32], x2 = xr[lane+64], x3 = xr[lane+96];
            float s0 = x0*w0a + x1*w1a + x2*w2a + x3*w3a;
            float s1 = x0*w0b + x1*w1b + x2*w2b + x3*w3b;
            float s2 = x0*w0c + x1*w1c + x2*w2c + x3*w3c;
            #pragma unroll
            for (int o = 16; o; o >>= 1) {
                s0 += __shfl_xor_sync(0xffffffffu, s0, o);
                s1 += __shfl_xor_sync(0xffffffffu, s1, o);
                s2 += __shfl_xor_sync(0xffffffffu, s2, o);
            }
            if (lane == 0) {
                float om = 1.f / (1.f + expf(s0 + b0));       // 1 - sigmoid
                float e  = 1.f / (1.f + expf(-(s1 + b1)));
                float th = 1.f / (1.f + expf(-(s2 + b2)));
                g_g4[r] = make_float4(om, e, th, 0.f);
            }
        }
        return;
    }
    extern __shared__ __nv_bfloat16 bsm[];
    __nv_bfloat16* __restrict__ XH  = bsm;
    __nv_bfloat16* __restrict__ XL  = XH  + 128*KP;
    __nv_bfloat16* __restrict__ WTH = XL  + 128*KP;
    __nv_bfloat16* __restrict__ WTL = WTH + 128*KP;

    const float* __restrict__ W = (which == 0) ? Wk : ((which == 1) ? Wv : Wq);
    float* __restrict__ out = (which == 0) ? g_k : ((which == 1) ? g_v : g_q);
    const int rowBase = blockIdx.x * 128;

    const int tid  = threadIdx.x;
    const int lane = tid & 31;
    const int warp = tid >> 5;
    const int g    = lane >> 2;
    const int tig  = lane & 3;
    const int wm   = warp >> 1;
    const int wn   = warp & 1;

    float acc[2][8][4];
    #pragma unroll
    for (int mt = 0; mt < 2; mt++)
        #pragma unroll
        for (int nt = 0; nt < 8; nt++)
            #pragma unroll
            for (int r = 0; r < 4; r++) acc[mt][nt][r] = 0.f;

    for (int k0 = 0; k0 < 128; k0 += 64) {
        {
            const int row = tid >> 1, half = tid & 1;
            const float* __restrict__ src = x + (rowBase + row)*ND + k0 + half*32;
            __nv_bfloat16* __restrict__ dh = XH + row*KP + half*32;
            __nv_bfloat16* __restrict__ dl = XL + row*KP + half*32;
            #pragma unroll
            for (int j = 0; j < 8; j++) {
                float4 v = *reinterpret_cast<const float4*>(&src[j*4]);
                #pragma unroll
                for (int i = 0; i < 4; i++) {
                    __nv_bfloat16 h, l;
                    bf16split((&v.x)[i], h, l);
                    dh[j*4+i] = h; dl[j*4+i] = l;
                }
            }
        }
        {
            const int krow = tid >> 2, nb = (tid & 3)*32;
            const float* __restrict__ src = W + (k0 + krow)*ND + nb;
            #pragma unroll
            for (int j = 0; j < 8; j++) {
                float4 v = *reinterpret_cast<const float4*>(&src[j*4]);
                #pragma unroll
                for (int i = 0; i < 4; i++) {
                    __nv_bfloat16 h, l;
                    bf16split((&v.x)[i], h, l);
                    const int n = nb + j*4 + i;
                    WTH[n*KP + krow] = h;
                    WTL[n*KP + krow] = l;
                }
            }
        }
        __syncthreads();

        #pragma unroll
        for (int kk = 0; kk < 64; kk += 16) {
            unsigned ah[2][4], al[2][4];
            #pragma unroll
            for (int mt = 0; mt < 2; mt++) {
                const int r0 = (wm*32 + mt*16 + g)*KP + kk + tig*2;
                const int r1 = r0 + 8*KP;
                ah[mt][0] = *reinterpret_cast<const unsigned*>(&XH[r0]);
                ah[mt][1] = *reinterpret_cast<const unsigned*>(&XH[r1]);
                ah[mt][2] = *reinterpret_cast<const unsigned*>(&XH[r0 + 8]);
                ah[mt][3] = *reinterpret_cast<const unsigned*>(&XH[r1 + 8]);
                al[mt][0] = *reinterpret_cast<const unsigned*>(&XL[r0]);
                al[mt][1] = *reinterpret_cast<const unsigned*>(&XL[r1]);
                al[mt][2] = *reinterpret_cast<const unsigned*>(&XL[r0 + 8]);
                al[mt][3] = *reinterpret_cast<const unsigned*>(&XL[r1 + 8]);
            }
            #pragma unroll
            for (int nt = 0; nt < 8; nt++) {
                const int bo = (wn*64 + nt*8 + g)*KP + kk + tig*2;
                unsigned bh[2], bl[2];
                bh[0] = *reinterpret_cast<const unsigned*>(&WTH[bo]);
                bh[1] = *reinterpret_cast<const unsigned*>(&WTH[bo + 8]);
                bl[0] = *reinterpret_cast<const unsigned*>(&WTL[bo]);
                bl[1] = *reinterpret_cast<const unsigned*>(&WTL[bo + 8]);
                #pragma unroll
                for (int mt = 0; mt < 2; mt++) {
                    mma16816(acc[mt][nt], ah[mt], bh);
                    mma16816(acc[mt][nt], ah[mt], bl);
                    mma16816(acc[mt][nt], al[mt], bh);
                }
            }
        }
        __syncthreads();
    }

    #pragma unroll
    for (int mt = 0; mt < 2; mt++) {
        const int r0 = rowBase + wm*32 + mt*16 + g;
        const int r1 = r0 + 8;
        #pragma unroll
        for (int nt = 0; nt < 8; nt++) {
            const int c0 = wn*64 + nt*8 + tig*2;
            *reinterpret_cast<float2*>(&out[r0*ND + c0]) = make_float2(acc[mt][nt][0], acc[mt][nt][1]);
            *reinterpret_cast<float2*>(&out[r1*ND + c0]) = make_float2(acc[mt][nt][2], acc[mt][nt][3]);
        }
    }
}

// ============================================================
// Pass 1: coarse chunk map composition (diag maps + weight maps)
// ============================================================
__global__ __launch_bounds__(128) void pass1_kernel()
{
    const int blk = blockIdx.x;
    if (blk < NB*NC) {
        const int b = blk >> 4, c = blk & (NC-1);
        const int i = threadIdx.x;
        const int t0 = c * LC;
        const float*  __restrict__ kp = g_k + (b*NS + t0)*ND + i;
        const float*  __restrict__ vp = g_v + (b*NS + t0)*ND + i;
        const float4* __restrict__ gp = g_g4 + b*NS + t0;

        float m00=1.f, m01=0.f, m10=0.f, m11=1.f, w0=0.f, w1=0.f;
        float kA[UG], vA[UG], kB[UG], vB[UG];
        float4 gA[UG], gB[UG];
        #pragma unroll
        for (int s = 0; s < UG; s++) { kA[s]=kp[s*ND]; vA[s]=vp[s*ND]; gA[s]=gp[s]; }

        #pragma unroll
        for (int g = 0; g < NGRP; g++) {
            const bool useA = ((g & 1) == 0);
            if (g + 1 < NGRP) {
                #pragma unroll
                for (int s = 0; s < UG; s++) {
                    int off = ((g+1)*UG + s)*ND;
                    int go  = (g+1)*UG + s;
                    if (useA) { kB[s]=kp[off]; vB[s]=vp[off]; gB[s]=gp[go]; }
                    else      { kA[s]=kp[off]; vA[s]=vp[off]; gA[s]=gp[go]; }
                }
            }
            #pragma unroll
            for (int s = 0; s < UG; s++) {
                float  kk = useA ? kA[s] : kB[s];
                float  vv = useA ? vA[s] : vB[s];
                float4 gg = useA ? gA[s] : gB[s];
                float om = gg.x, e = gg.y, th = gg.z;
                float t1 = th*kk, c2 = t1*vv, d0 = -t1*kk, a00 = om + d0;
                float te0 = e*m10, te1 = e*m11;
                float n00 = fmaf(a00, m00, te0), n10 = fmaf(d0, m00, te0);
                float n01 = fmaf(a00, m01, te1), n11 = fmaf(d0, m01, te1);
                float tev = fmaf(e, w1, c2);
                float nw0 = fmaf(a00, w0, tev), nw1 = fmaf(d0, w0, tev);
                m00=n00; m01=n01; m10=n10; m11=n11; w0=nw0; w1=nw1;
            }
        }
        const int base = (b*NC + c)*ND + i;
        const int ST = NB*NC*ND;
        g_dmap[0*ST+base] = m00; g_dmap[1*ST+base] = m01;
        g_dmap[2*ST+base] = m10; g_dmap[3*ST+base] = m11;
        g_dmap[4*ST+base] = w0;  g_dmap[5*ST+base] = w1;
    } else {
        const int u = threadIdx.x;
        const int b = u >> 4, wc = u & (NC-1);
        const float4* __restrict__ gp = g_g4 + b*NS + wc*LC;
        float ph = 1.f, qh = 1.f, gh = 0.f;
        #pragma unroll 4
        for (int s = LC-1; s >= 0; s--) {
            float4 g = gp[s];
            float p = g.x, q = g.y;
            gh = fmaf(q, gh, p*ph);
            ph *= p;
            qh *= q;
        }
        g_wmap[0*NB*NC + u] = ph;
        g_wmap[1*NB*NC + u] = qh;
        g_wmap[2*NB*NC + u] = gh;
    }
}

// ============================================================
// Fused pass 3 (pass2 inlined): per (b, coarse chunk) block, 512 threads
// ============================================================
#define F3_ENT_OFF   65536
#define F3_FM_OFF    (65536 + 49152)
#define F3_SG_OFF    176128
#define F3_SA_OFF    177152
#define F3_WENT_OFF  177664
#define F3_SMEM      177920

__global__ __launch_bounds__(512) void fused3_kernel(float* __restrict__ d_out)
{
    extern __shared__ char smc[];
    float* __restrict__ Kraw = reinterpret_cast<float*>(smc);            // [64][128]
    float* __restrict__ Eraw = Kraw + LC*ND;                             // [64][128]
    float* __restrict__ ENT  = reinterpret_cast<float*>(smc + F3_ENT_OFF);  // [6][16][128]
    float* __restrict__ fm   = reinterpret_cast<float*>(smc + F3_FM_OFF);   // [6][4][128]
    float4* __restrict__ sG  = reinterpret_cast<float4*>(smc + F3_SG_OFF);  // [64]
    float* __restrict__ sA   = reinterpret_cast<float*>(smc + F3_SA_OFF);   // [64]
    float* __restrict__ sB   = sA + LC;                                  // [64]
    float* __restrict__ wENT = reinterpret_cast<float*>(smc + F3_WENT_OFF); // [16][3]
    float* __restrict__ wfm  = wENT + 48;                                // [4][3]
    __nv_bfloat16* __restrict__ KAh = reinterpret_cast<__nv_bfloat16*>(smc + F3_ENT_OFF);
    __nv_bfloat16* __restrict__ KAl = KAh + ND*KP;
    __nv_bfloat16* __restrict__ KBh = KAl + ND*KP;
    __nv_bfloat16* __restrict__ KBl = KBh + ND*KP;
    __nv_bfloat16* __restrict__ ETh = KBl + ND*KP;
    __nv_bfloat16* __restrict__ ETl = ETh + ND*KP;

    const int b = blockIdx.x >> 4, c = blockIdx.x & (NC-1);
    const int tid = threadIdx.x;
    const int sub = tid >> 7, i = tid & 127;
    const int t0f = c*LC + sub*LF;
    const float*  __restrict__ kp = g_k + (b*NS + t0f)*ND + i;
    const float*  __restrict__ vp = g_v + (b*NS + t0f)*ND + i;
    const float*  __restrict__ qp = g_q + (b*NS + t0f)*ND + i;
    const float4* __restrict__ gp = g_g4 + b*NS + t0f;

    // ---- cooperative prefetch of coarse maps (entry-state inputs) ----
    {
        const int ST = NB*NC*ND;
        const int nEl = c * 128;
        #pragma unroll
        for (int jj = 0; jj < 6; jj++)
            for (int u = tid; u < nEl; u += 512)
                ENT[jj*2048 + u] = g_dmap[jj*ST + b*NC*ND + u];
        if (tid < 48) {
            const int t = tid / 3, j = tid % 3;
            wENT[t*3 + j] = g_wmap[j*NB*NC + b*NC + t];
        }
    }
    // gates -> smem (per sub, 16 threads)
    if (i < LF) sG[sub*LF + i] = gp[i];

    // ---- A0: compose fine diag map over LF=16 steps; stage k/v to smem ----
    {
        float m00=1.f, m01=0.f, m10=0.f, m11=1.f, w0=0.f, w1=0.f;
        float kA[4], vA[4], kB[4], vB[4];
        float4 gA[4], gB[4];
        #pragma unroll
        for (int s = 0; s < 4; s++) { kA[s]=kp[s*ND]; vA[s]=vp[s*ND]; gA[s]=gp[s]; }
        #pragma unroll
        for (int g = 0; g < 4; g++) {
            const bool useA = ((g & 1) == 0);
            if (g < 3) {
                #pragma unroll
                for (int s = 0; s < 4; s++) {
                    int off = ((g+1)*4 + s)*ND, go = (g+1)*4 + s;
                    if (useA) { kB[s]=kp[off]; vB[s]=vp[off]; gB[s]=gp[go]; }
                    else      { kA[s]=kp[off]; vA[s]=vp[off]; gA[s]=gp[go]; }
                }
            }
            #pragma unroll
            for (int s = 0; s < 4; s++) {
                float  kk = useA ? kA[s] : kB[s];
                float  vv = useA ? vA[s] : vB[s];
                float4 gg = useA ? gA[s] : gB[s];
                const int row = sub*LF + g*4 + s;
                Kraw[row*ND + i] = kk;
                Eraw[row*ND + i] = vv;
                float om = gg.x, e = gg.y, th = gg.z;
                float t1 = th*kk, c2 = t1*vv, d0 = -t1*kk, a00 = om + d0;
                float te0 = e*m10, te1 = e*m11;
                float n00 = fmaf(a00, m00, te0), n10 = fmaf(d0, m00, te0);
                float n01 = fmaf(a00, m01, te1), n11 = fmaf(d0, m01, te1);
                float tev = fmaf(e, w1, c2);
                float nw0 = fmaf(a00, w0, tev), nw1 = fmaf(d0, w0, tev);
                m00=n00; m01=n01; m10=n10; m11=n11; w0=nw0; w1=nw1;
            }
        }
        fm[(0*4+sub)*128+i] = m00; fm[(1*4+sub)*128+i] = m01;
        fm[(2*4+sub)*128+i] = m10; fm[(3*4+sub)*128+i] = m11;
        fm[(4*4+sub)*128+i] = w0;  fm[(5*4+sub)*128+i] = w1;
    }
    if (i == 0) {
        // fine weight map for this sub-chunk
        float ph = 1.f, qh = 1.f, gh = 0.f;
        #pragma unroll
        for (int s = LF-1; s >= 0; s--) {
            float4 g = gp[s];
            gh = fmaf(g.y, gh, g.x*ph);
            ph *= g.x;
            qh *= g.y;
        }
        wfm[sub*3+0] = ph; wfm[sub*3+1] = qh; wfm[sub*3+2] = gh;
    }
    __syncthreads();

    // ---- combine: coarse entry (over chunks t<c) then fine maps (t<sub) ----
    float dm = 0.f, ds = 0.f;
    for (int t = 0; t < c; t++) {
        float a00 = ENT[0*2048 + t*128 + i], a01 = ENT[1*2048 + t*128 + i];
        float a10 = ENT[2*2048 + t*128 + i], a11 = ENT[3*2048 + t*128 + i];
        float v0  = ENT[4*2048 + t*128 + i], v1  = ENT[5*2048 + t*128 + i];
        float n0 = fmaf(a00, dm, fmaf(a01, ds, v0));
        float n1 = fmaf(a10, dm, fmaf(a11, ds, v1));
        dm = n0; ds = n1;
    }
    for (int t = 0; t < sub; t++) {
        float a00 = fm[(0*4+t)*128+i], a01 = fm[(1*4+t)*128+i];
        float a10 = fm[(2*4+t)*128+i], a11 = fm[(3*4+t)*128+i];
        float v0  = fm[(4*4+t)*128+i], v1  = fm[(5*4+t)*128+i];
        float n0 = fmaf(a00, dm, fmaf(a01, ds, v0));
        float n1 = fmaf(a10, dm, fmaf(a11, ds, v1));
        dm = n0; ds = n1;
    }

    if (i == 0) {
        // coarse weight entry (chunks t>c) then fine (t>sub), then 16-step scan
        float P = 1.f, E = 1.f, w = 1.f;
        for (int t = NC-1; t > c; t--) {
            float ph = wENT[t*3+0], qh = wENT[t*3+1], gh = wENT[t*3+2];
            float nw = fmaf(qh, w, gh*P);
            P *= ph; E *= qh; w = nw;
        }
        for (int t = 3; t > sub; t--) {
            float ph = wfm[t*3+0], qh = wfm[t*3+1], gh = wfm[t*3+2];
            float nw = fmaf(qh, w, gh*P);
            P *= ph; E *= qh; w = nw;
        }
        #pragma unroll
        for (int s = LF-1; s >= 0; s--) {
            float4 g = sG[sub*LF + s];
            float th = g.z;
            sA[sub*LF + s] = -th * w;
            sB[sub*LF + s] = -th * E;
            P *= g.x;
            E *= g.y;
            w  = fmaf(g.y, w, P);
        }
    }

    // ---- A1: replay LF=16 steps from smem (q prefetched to regs) ----
    {
        float* __restrict__ op = d_out + (b*NS + t0f)*ND + i;
        float q16[LF];
        #pragma unroll
        for (int s = 0; s < LF; s++) q16[s] = qp[s*ND];
        #pragma unroll
        for (int st = 0; st < LF; st++) {
            const int row = sub*LF + st;
            float4 gg = sG[row];
            float  kk = Kraw[row*ND + i];
            float  vv = Eraw[row*ND + i];
            float om = gg.x, e = gg.y, th = gg.z;
            op[st*ND] = q16[st] * dm;
            float err = fmaf(kk, dm, -vv);
            Eraw[row*ND + i] = err;
            float t1 = th*kk, c2 = t1*vv, d0 = -t1*kk;
            float inner = fmaf(e, ds, c2);
            ds = fmaf(d0, dm, inner);
            dm = fmaf(om, dm, ds);
        }
    }
    __syncthreads();

    // ---- phase B: convert + weight + transpose (overlays ENT/fm) ----
    #pragma unroll
    for (int r = 0; r < 16; r++) {
        const int idx = tid + r*512;        // = s*ND + i2
        const int s = idx >> 7, i2 = idx & 127;
        const float kf = Kraw[idx];
        const float ef = Eraw[idx];
        const float pa = sA[s] * kf;
        const float pb = sB[s] * kf;
        __nv_bfloat16 h, l;
        bf16split(pa, h, l); KAh[i2*KP + s] = h; KAl[i2*KP + s] = l;
        bf16split(pb, h, l); KBh[i2*KP + s] = h; KBl[i2*KP + s] = l;
        bf16split(ef, h, l); ETh[i2*KP + s] = h; ETl[i2*KP + s] = l;
    }
    __syncthreads();

    // ---- phase C: tensor-core weighted outer products ----
    const int which = tid >> 8;
    const int t256 = tid & 255;
    const int lane = t256 & 31, warp = t256 >> 5;
    const int g = lane >> 2, tig = lane & 3;
    const int wm = warp >> 1, wn = warp & 1;
    const __nv_bfloat16* __restrict__ Ah = which ? KBh : KAh;
    const __nv_bfloat16* __restrict__ Al = which ? KBl : KAl;

    float acc[2][8][4];
    #pragma unroll
    for (int mt = 0; mt < 2; mt++)
        #pragma unroll
        for (int nt = 0; nt < 8; nt++)
            #pragma unroll
            for (int r = 0; r < 4; r++) acc[mt][nt][r] = 0.f;

    #pragma unroll
    for (int kk = 0; kk < LC; kk += 16) {
        unsigned ah[2][4], al[2][4];
        #pragma unroll
        for (int mt = 0; mt < 2; mt++) {
            const int r0 = (wm*32 + mt*16 + g)*KP + kk + tig*2;
            const int r1 = r0 + 8*KP;
            ah[mt][0] = *reinterpret_cast<const unsigned*>(&Ah[r0]);
            ah[mt][1] = *reinterpret_cast<const unsigned*>(&Ah[r1]);
            ah[mt][2] = *reinterpret_cast<const unsigned*>(&Ah[r0 + 8]);
            ah[mt][3] = *reinterpret_cast<const unsigned*>(&Ah[r1 + 8]);
            al[mt][0] = *reinterpret_cast<const unsigned*>(&Al[r0]);
            al[mt][1] = *reinterpret_cast<const unsigned*>(&Al[r1]);
            al[mt][2] = *reinterpret_cast<const unsigned*>(&Al[r0 + 8]);
            al[mt][3] = *reinterpret_cast<const unsigned*>(&Al[r1 + 8]);
        }
        #pragma unroll
        for (int nt = 0; nt < 8; nt++) {
            const int bo = (wn*64 + nt*8 + g)*KP + kk + tig*2;
            unsigned bh[2], bl[2];
            bh[0] = *reinterpret_cast<const unsigned*>(&ETh[bo]);
            bh[1] = *reinterpret_cast<const unsigned*>(&ETh[bo + 8]);
            bl[0] = *reinterpret_cast<const unsigned*>(&ETl[bo]);
            bl[1] = *reinterpret_cast<const unsigned*>(&ETl[bo + 8]);
            #pragma unroll
            for (int mt = 0; mt < 2; mt++) {
                mma16816(acc[mt][nt], ah[mt], bh);
                mma16816(acc[mt][nt], ah[mt], bl);
                mma16816(acc[mt][nt], al[mt], bh);
            }
        }
    }

    float* __restrict__ C = g_part + ((b*2 + which)*NC + c)*ND*ND;
    #pragma unroll
    for (int mt = 0; mt < 2; mt++) {
        const int r0 = wm*32 + mt*16 + g;
        const int r1 = r0 + 8;
        #pragma unroll
        for (int nt = 0; nt < 8; nt++) {
            const int c0 = wn*64 + nt*8 + tig*2;
            *reinterpret_cast<float2*>(&C[r0*ND + c0]) = make_float2(acc[mt][nt][0], acc[mt][nt][1]);
            *reinterpret_cast<float2*>(&C[r1*ND + c0]) = make_float2(acc[mt][nt][2], acc[mt][nt][3]);
        }
    }
}

// ============================================================
// Kernel 5: reduce split partials -> d_out tail (float4, MLP=16 prefetch)
// ============================================================
__global__ __launch_bounds__(128) void reduce_kernel(float* __restrict__ d_out)
{
    const int g4 = blockIdx.x * 128 + threadIdx.x;   // [0, 65536) float4 units
    const int gid = g4 * 4;
    const int which = gid >> 17;
    const int r  = gid & 131071;
    const int b  = r >> 14;
    const int ij = r & 16383;
    const float* __restrict__ p = g_part + ((b*2 + which)*NC)*ND*ND + ij;

    // force all 16 loads in flight before summing
    float4 t[NC];
    #pragma unroll
    for (int sp = 0; sp < NC; sp++)
        t[sp] = *reinterpret_cast<const float4*>(&p[sp*ND*ND]);

    // pairwise tree sum
    #pragma unroll
    for (int stride = 1; stride < NC; stride <<= 1)
        #pragma unroll
        for (int sp = 0; sp < NC; sp += stride*2) {
            t[sp].x += t[sp+stride].x; t[sp].y += t[sp+stride].y;
            t[sp].z += t[sp+stride].z; t[sp].w += t[sp+stride].w;
        }
    *reinterpret_cast<float4*>(&d_out[BSD + gid]) = t[0];
}

// ============================================================
extern "C" void kernel_launch(void* const* d_in, const int* in_sizes, int n_in,
                              void* d_out, int out_size)
{
    const float* x  = (const float*)d_in[0];
    const float* Wk = (const float*)d_in[1];
    const float* Wv = (const float*)d_in[2];
    const float* Wq = (const float*)d_in[3];
    const float* Wg = (const float*)d_in[4];
    const float* bg = (const float*)d_in[5];
    float* out = (float*)d_out;

    const int k1_smem = 4 * 128 * KP * (int)sizeof(__nv_bfloat16);  // 73728 B
    cudaFuncSetAttribute(k1_qkv_gates, cudaFuncAttributeMaxDynamicSharedMemorySize, k1_smem);
    cudaFuncSetAttribute(fused3_kernel, cudaFuncAttributeMaxDynamicSharedMemorySize, F3_SMEM);

    k1_qkv_gates<<<dim3(64, 4), 256, k1_smem>>>(x, Wk, Wv, Wq, Wg, bg);
    pass1_kernel<<<NB*NC + 1, 128>>>();
    fused3_kernel<<<NB*NC, 512, F3_SMEM>>>(out);
    reduce_kernel<<<512, 128>>>(out);
}

// round 10
// speedup vs baseline: 1.0065x; 1.0065x over previous
#include <cuda_runtime.h>
#include <cuda_bf16.h>

#define NB 8
#define NS 1024
#define ND 128
#define NROWS (NB*NS)   // 8192
#define BSD (NB*NS*ND)  // 1048576

#define NC 16           // coarse chunks (GEMM splits)
#define LC 64           // steps per coarse chunk
#define LF 16           // steps per fine sub-chunk (replay granularity)
#define UG 8            // prefetch group size (pass1)
#define NGRP (LC/UG)

#define KP 72           // padded bf16 k-stride in smem (conflict-free frag loads)

// ---- scratch (static device globals; no runtime allocation) ----
__device__ float  g_k[NROWS*ND];
__device__ float  g_v[NROWS*ND];
__device__ float  g_q[NROWS*ND];
__device__ float4 g_g4[NROWS];           // (om=1-a, e, th, 0) per (b,t)
__device__ float  g_dmap[6*NB*NC*ND];    // composed coarse diag maps
__device__ float  g_wmap[3*NB*NC];
__device__ float  g_part[NB*2*NC*ND*ND];

// ---- mma.sync m16n8k16 bf16 -> f32 ----
__device__ __forceinline__ void mma16816(float* c, const unsigned* a, const unsigned* b)
{
    asm volatile(
        "mma.sync.aligned.m16n8k16.row.col.f32.bf16.bf16.f32 "
        "{%0,%1,%2,%3}, {%4,%5,%6,%7}, {%8,%9}, {%0,%1,%2,%3};"
        : "+f"(c[0]), "+f"(c[1]), "+f"(c[2]), "+f"(c[3])
        : "r"(a[0]), "r"(a[1]), "r"(a[2]), "r"(a[3]), "r"(b[0]), "r"(b[1]));
}

__device__ __forceinline__ void bf16split(float f, __nv_bfloat16& h, __nv_bfloat16& l)
{
    h = __float2bfloat16_rn(f);
    l = __float2bfloat16_rn(f - __bfloat162float(h));
}

// ============================================================
// Kernel 1: y<3: k/v/q = x@W via bf16-split tensor mma; y==3: gates
// ============================================================
__global__ __launch_bounds__(256) void k1_qkv_gates(
    const float* __restrict__ x, const float* __restrict__ Wk,
    const float* __restrict__ Wv, const float* __restrict__ Wq,
    const float* __restrict__ Wg, const float* __restrict__ bg)
{
    const int which = blockIdx.y;
    if (which == 3) {
        const int base = blockIdx.x * 128;
        const int w = threadIdx.x >> 5, lane = threadIdx.x & 31;
        const float b0 = bg[0], b1 = bg[1], b2 = bg[2];
        const float w0a = Wg[lane*3+0],      w0b = Wg[lane*3+1],      w0c = Wg[lane*3+2];
        const float w1a = Wg[(lane+32)*3+0], w1b = Wg[(lane+32)*3+1], w1c = Wg[(lane+32)*3+2];
        const float w2a = Wg[(lane+64)*3+0], w2b = Wg[(lane+64)*3+1], w2c = Wg[(lane+64)*3+2];
        const float w3a = Wg[(lane+96)*3+0], w3b = Wg[(lane+96)*3+1], w3c = Wg[(lane+96)*3+2];
        for (int rr = 0; rr < 16; rr++) {
            const int r = base + w*16 + rr;
            const float* __restrict__ xr = x + r * ND;
            float x0 = xr[lane], x1 = xr[lane+32], x2 = xr[lane+64], x3 = xr[lane+96];
            float s0 = x0*w0a + x1*w1a + x2*w2a + x3*w3a;
            float s1 = x0*w0b + x1*w1b + x2*w2b + x3*w3b;
            float s2 = x0*w0c + x1*w1c + x2*w2c + x3*w3c;
            #pragma unroll
            for (int o = 16; o; o >>= 1) {
                s0 += __shfl_xor_sync(0xffffffffu, s0, o);
                s1 += __shfl_xor_sync(0xffffffffu, s1, o);
                s2 += __shfl_xor_sync(0xffffffffu, s2, o);
            }
            if (lane == 0) {
                float om = 1.f / (1.f + expf(s0 + b0));       // 1 - sigmoid
                float e  = 1.f / (1.f + expf(-(s1 + b1)));
                float th = 1.f / (1.f + expf(-(s2 + b2)));
                g_g4[r] = make_float4(om, e, th, 0.f);
            }
        }
        return;
    }
    extern __shared__ __nv_bfloat16 bsm[];
    __nv_bfloat16* __restrict__ XH  = bsm;
    __nv_bfloat16* __restrict__ XL  = XH  + 128*KP;
    __nv_bfloat16* __restrict__ WTH = XL  + 128*KP;
    __nv_bfloat16* __restrict__ WTL = WTH + 128*KP;

    const float* __restrict__ W = (which == 0) ? Wk : ((which == 1) ? Wv : Wq);
    float* __restrict__ out = (which == 0) ? g_k : ((which == 1) ? g_v : g_q);
    const int rowBase = blockIdx.x * 128;

    const int tid  = threadIdx.x;
    const int lane = tid & 31;
    const int warp = tid >> 5;
    const int g    = lane >> 2;
    const int tig  = lane & 3;
    const int wm   = warp >> 1;
    const int wn   = warp & 1;

    float acc[2][8][4];
    #pragma unroll
    for (int mt = 0; mt < 2; mt++)
        #pragma unroll
        for (int nt = 0; nt < 8; nt++)
            #pragma unroll
            for (int r = 0; r < 4; r++) acc[mt][nt][r] = 0.f;

    for (int k0 = 0; k0 < 128; k0 += 64) {
        {
            const int row = tid >> 1, half = tid & 1;
            const float* __restrict__ src = x + (rowBase + row)*ND + k0 + half*32;
            __nv_bfloat16* __restrict__ dh = XH + row*KP + half*32;
            __nv_bfloat16* __restrict__ dl = XL + row*KP + half*32;
            #pragma unroll
            for (int j = 0; j < 8; j++) {
                float4 v = *reinterpret_cast<const float4*>(&src[j*4]);
                #pragma unroll
                for (int i = 0; i < 4; i++) {
                    __nv_bfloat16 h, l;
                    bf16split((&v.x)[i], h, l);
                    dh[j*4+i] = h; dl[j*4+i] = l;
                }
            }
        }
        {
            const int krow = tid >> 2, nb = (tid & 3)*32;
            const float* __restrict__ src = W + (k0 + krow)*ND + nb;
            #pragma unroll
            for (int j = 0; j < 8; j++) {
                float4 v = *reinterpret_cast<const float4*>(&src[j*4]);
                #pragma unroll
                for (int i = 0; i < 4; i++) {
                    __nv_bfloat16 h, l;
                    bf16split((&v.x)[i], h, l);
                    const int n = nb + j*4 + i;
                    WTH[n*KP + krow] = h;
                    WTL[n*KP + krow] = l;
                }
            }
        }
        __syncthreads();

        #pragma unroll
        for (int kk = 0; kk < 64; kk += 16) {
            unsigned ah[2][4], al[2][4];
            #pragma unroll
            for (int mt = 0; mt < 2; mt++) {
                const int r0 = (wm*32 + mt*16 + g)*KP + kk + tig*2;
                const int r1 = r0 + 8*KP;
                ah[mt][0] = *reinterpret_cast<const unsigned*>(&XH[r0]);
                ah[mt][1] = *reinterpret_cast<const unsigned*>(&XH[r1]);
                ah[mt][2] = *reinterpret_cast<const unsigned*>(&XH[r0 + 8]);
                ah[mt][3] = *reinterpret_cast<const unsigned*>(&XH[r1 + 8]);
                al[mt][0] = *reinterpret_cast<const unsigned*>(&XL[r0]);
                al[mt][1] = *reinterpret_cast<const unsigned*>(&XL[r1]);
                al[mt][2] = *reinterpret_cast<const unsigned*>(&XL[r0 + 8]);
                al[mt][3] = *reinterpret_cast<const unsigned*>(&XL[r1 + 8]);
            }
            #pragma unroll
            for (int nt = 0; nt < 8; nt++) {
                const int bo = (wn*64 + nt*8 + g)*KP + kk + tig*2;
                unsigned bh[2], bl[2];
                bh[0] = *reinterpret_cast<const unsigned*>(&WTH[bo]);
                bh[1] = *reinterpret_cast<const unsigned*>(&WTH[bo + 8]);
                bl[0] = *reinterpret_cast<const unsigned*>(&WTL[bo]);
                bl[1] = *reinterpret_cast<const unsigned*>(&WTL[bo + 8]);
                #pragma unroll
                for (int mt = 0; mt < 2; mt++) {
                    mma16816(acc[mt][nt], ah[mt], bh);
                    mma16816(acc[mt][nt], ah[mt], bl);
                    mma16816(acc[mt][nt], al[mt], bh);
                }
            }
        }
        __syncthreads();
    }

    #pragma unroll
    for (int mt = 0; mt < 2; mt++) {
        const int r0 = rowBase + wm*32 + mt*16 + g;
        const int r1 = r0 + 8;
        #pragma unroll
        for (int nt = 0; nt < 8; nt++) {
            const int c0 = wn*64 + nt*8 + tig*2;
            *reinterpret_cast<float2*>(&out[r0*ND + c0]) = make_float2(acc[mt][nt][0], acc[mt][nt][1]);
            *reinterpret_cast<float2*>(&out[r1*ND + c0]) = make_float2(acc[mt][nt][2], acc[mt][nt][3]);
        }
    }
}

// ============================================================
// Pass 1: coarse chunk map composition (diag maps + weight maps)
// ============================================================
__global__ __launch_bounds__(128) void pass1_kernel()
{
    const int blk = blockIdx.x;
    if (blk < NB*NC) {
        const int b = blk >> 4, c = blk & (NC-1);
        const int i = threadIdx.x;
        const int t0 = c * LC;
        const float*  __restrict__ kp = g_k + (b*NS + t0)*ND + i;
        const float*  __restrict__ vp = g_v + (b*NS + t0)*ND + i;
        const float4* __restrict__ gp = g_g4 + b*NS + t0;

        float m00=1.f, m01=0.f, m10=0.f, m11=1.f, w0=0.f, w1=0.f;
        float kA[UG], vA[UG], kB[UG], vB[UG];
        float4 gA[UG], gB[UG];
        #pragma unroll
        for (int s = 0; s < UG; s++) { kA[s]=kp[s*ND]; vA[s]=vp[s*ND]; gA[s]=gp[s]; }

        #pragma unroll
        for (int g = 0; g < NGRP; g++) {
            const bool useA = ((g & 1) == 0);
            if (g + 1 < NGRP) {
                #pragma unroll
                for (int s = 0; s < UG; s++) {
                    int off = ((g+1)*UG + s)*ND;
                    int go  = (g+1)*UG + s;
                    if (useA) { kB[s]=kp[off]; vB[s]=vp[off]; gB[s]=gp[go]; }
                    else      { kA[s]=kp[off]; vA[s]=vp[off]; gA[s]=gp[go]; }
                }
            }
            #pragma unroll
            for (int s = 0; s < UG; s++) {
                float  kk = useA ? kA[s] : kB[s];
                float  vv = useA ? vA[s] : vB[s];
                float4 gg = useA ? gA[s] : gB[s];
                float om = gg.x, e = gg.y, th = gg.z;
                float t1 = th*kk, c2 = t1*vv, d0 = -t1*kk, a00 = om + d0;
                float te0 = e*m10, te1 = e*m11;
                float n00 = fmaf(a00, m00, te0), n10 = fmaf(d0, m00, te0);
                float n01 = fmaf(a00, m01, te1), n11 = fmaf(d0, m01, te1);
                float tev = fmaf(e, w1, c2);
                float nw0 = fmaf(a00, w0, tev), nw1 = fmaf(d0, w0, tev);
                m00=n00; m01=n01; m10=n10; m11=n11; w0=nw0; w1=nw1;
            }
        }
        const int base = (b*NC + c)*ND + i;
        const int ST = NB*NC*ND;
        g_dmap[0*ST+base] = m00; g_dmap[1*ST+base] = m01;
        g_dmap[2*ST+base] = m10; g_dmap[3*ST+base] = m11;
        g_dmap[4*ST+base] = w0;  g_dmap[5*ST+base] = w1;
    } else {
        const int u = threadIdx.x;
        const int b = u >> 4, wc = u & (NC-1);
        const float4* __restrict__ gp = g_g4 + b*NS + wc*LC;
        float ph = 1.f, qh = 1.f, gh = 0.f;
        #pragma unroll 4
        for (int s = LC-1; s >= 0; s--) {
            float4 g = gp[s];
            float p = g.x, q = g.y;
            gh = fmaf(q, gh, p*ph);
            ph *= p;
            qh *= q;
        }
        g_wmap[0*NB*NC + u] = ph;
        g_wmap[1*NB*NC + u] = qh;
        g_wmap[2*NB*NC + u] = gh;
    }
}

// ============================================================
// Fused pass 3 (pass2 inlined): per (b, coarse chunk) block, 512 threads
// ============================================================
#define F3_ENT_OFF   65536
#define F3_FM_OFF    (65536 + 49152)
#define F3_SG_OFF    176128
#define F3_SA_OFF    177152
#define F3_WENT_OFF  177664
#define F3_SMEM      177920

__global__ __launch_bounds__(512) void fused3_kernel(float* __restrict__ d_out)
{
    extern __shared__ char smc[];
    float* __restrict__ Kraw = reinterpret_cast<float*>(smc);            // [64][128]
    float* __restrict__ Eraw = Kraw + LC*ND;                             // [64][128]
    float* __restrict__ ENT  = reinterpret_cast<float*>(smc + F3_ENT_OFF);  // [6][16][128]
    float* __restrict__ fm   = reinterpret_cast<float*>(smc + F3_FM_OFF);   // [6][4][128]
    float4* __restrict__ sG  = reinterpret_cast<float4*>(smc + F3_SG_OFF);  // [64]
    float* __restrict__ sA   = reinterpret_cast<float*>(smc + F3_SA_OFF);   // [64]
    float* __restrict__ sB   = sA + LC;                                  // [64]
    float* __restrict__ wENT = reinterpret_cast<float*>(smc + F3_WENT_OFF); // [16][3]
    float* __restrict__ wfm  = wENT + 48;                                // [4][3]
    __nv_bfloat16* __restrict__ KAh = reinterpret_cast<__nv_bfloat16*>(smc + F3_ENT_OFF);
    __nv_bfloat16* __restrict__ KAl = KAh + ND*KP;
    __nv_bfloat16* __restrict__ KBh = KAl + ND*KP;
    __nv_bfloat16* __restrict__ KBl = KBh + ND*KP;
    __nv_bfloat16* __restrict__ ETh = KBl + ND*KP;
    __nv_bfloat16* __restrict__ ETl = ETh + ND*KP;

    const int b = blockIdx.x >> 4, c = blockIdx.x & (NC-1);
    const int tid = threadIdx.x;
    const int sub = tid >> 7, i = tid & 127;
    const int t0f = c*LC + sub*LF;
    const float*  __restrict__ kp = g_k + (b*NS + t0f)*ND + i;
    const float*  __restrict__ vp = g_v + (b*NS + t0f)*ND + i;
    const float*  __restrict__ qp = g_q + (b*NS + t0f)*ND + i;
    const float4* __restrict__ gp = g_g4 + b*NS + t0f;

    // ---- cooperative prefetch of coarse maps (entry-state inputs) ----
    {
        const int ST = NB*NC*ND;
        const int nEl = c * 128;
        #pragma unroll
        for (int jj = 0; jj < 6; jj++)
            for (int u = tid; u < nEl; u += 512)
                ENT[jj*2048 + u] = g_dmap[jj*ST + b*NC*ND + u];
        if (tid < 48) {
            const int t = tid / 3, j = tid % 3;
            wENT[t*3 + j] = g_wmap[j*NB*NC + b*NC + t];
        }
    }
    // gates -> smem (per sub, 16 threads)
    if (i < LF) sG[sub*LF + i] = gp[i];

    // ---- A0: compose fine diag map over LF=16 steps; stage k/v to smem ----
    {
        float m00=1.f, m01=0.f, m10=0.f, m11=1.f, w0=0.f, w1=0.f;
        float kA[4], vA[4], kB[4], vB[4];
        float4 gA[4], gB[4];
        #pragma unroll
        for (int s = 0; s < 4; s++) { kA[s]=kp[s*ND]; vA[s]=vp[s*ND]; gA[s]=gp[s]; }
        #pragma unroll
        for (int g = 0; g < 4; g++) {
            const bool useA = ((g & 1) == 0);
            if (g < 3) {
                #pragma unroll
                for (int s = 0; s < 4; s++) {
                    int off = ((g+1)*4 + s)*ND, go = (g+1)*4 + s;
                    if (useA) { kB[s]=kp[off]; vB[s]=vp[off]; gB[s]=gp[go]; }
                    else      { kA[s]=kp[off]; vA[s]=vp[off]; gA[s]=gp[go]; }
                }
            }
            #pragma unroll
            for (int s = 0; s < 4; s++) {
                float  kk = useA ? kA[s] : kB[s];
                float  vv = useA ? vA[s] : vB[s];
                float4 gg = useA ? gA[s] : gB[s];
                const int row = sub*LF + g*4 + s;
                Kraw[row*ND + i] = kk;
                Eraw[row*ND + i] = vv;
                float om = gg.x, e = gg.y, th = gg.z;
                float t1 = th*kk, c2 = t1*vv, d0 = -t1*kk, a00 = om + d0;
                float te0 = e*m10, te1 = e*m11;
                float n00 = fmaf(a00, m00, te0), n10 = fmaf(d0, m00, te0);
                float n01 = fmaf(a00, m01, te1), n11 = fmaf(d0, m01, te1);
                float tev = fmaf(e, w1, c2);
                float nw0 = fmaf(a00, w0, tev), nw1 = fmaf(d0, w0, tev);
                m00=n00; m01=n01; m10=n10; m11=n11; w0=nw0; w1=nw1;
            }
        }
        fm[(0*4+sub)*128+i] = m00; fm[(1*4+sub)*128+i] = m01;
        fm[(2*4+sub)*128+i] = m10; fm[(3*4+sub)*128+i] = m11;
        fm[(4*4+sub)*128+i] = w0;  fm[(5*4+sub)*128+i] = w1;
    }
    if (i == 0) {
        // fine weight map for this sub-chunk
        float ph = 1.f, qh = 1.f, gh = 0.f;
        #pragma unroll
        for (int s = LF-1; s >= 0; s--) {
            float4 g = gp[s];
            gh = fmaf(g.y, gh, g.x*ph);
            ph *= g.x;
            qh *= g.y;
        }
        wfm[sub*3+0] = ph; wfm[sub*3+1] = qh; wfm[sub*3+2] = gh;
    }
    __syncthreads();

    // ---- combine: coarse entry (over chunks t<c) then fine maps (t<sub) ----
    float dm = 0.f, ds = 0.f;
    for (int t = 0; t < c; t++) {
        float a00 = ENT[0*2048 + t*128 + i], a01 = ENT[1*2048 + t*128 + i];
        float a10 = ENT[2*2048 + t*128 + i], a11 = ENT[3*2048 + t*128 + i];
        float v0  = ENT[4*2048 + t*128 + i], v1  = ENT[5*2048 + t*128 + i];
        float n0 = fmaf(a00, dm, fmaf(a01, ds, v0));
        float n1 = fmaf(a10, dm, fmaf(a11, ds, v1));
        dm = n0; ds = n1;
    }
    for (int t = 0; t < sub; t++) {
        float a00 = fm[(0*4+t)*128+i], a01 = fm[(1*4+t)*128+i];
        float a10 = fm[(2*4+t)*128+i], a11 = fm[(3*4+t)*128+i];
        float v0  = fm[(4*4+t)*128+i], v1  = fm[(5*4+t)*128+i];
        float n0 = fmaf(a00, dm, fmaf(a01, ds, v0));
        float n1 = fmaf(a10, dm, fmaf(a11, ds, v1));
        dm = n0; ds = n1;
    }

    if (i == 0) {
        // coarse weight entry (chunks t>c) then fine (t>sub), then 16-step scan
        float P = 1.f, E = 1.f, w = 1.f;
        for (int t = NC-1; t > c; t--) {
            float ph = wENT[t*3+0], qh = wENT[t*3+1], gh = wENT[t*3+2];
            float nw = fmaf(qh, w, gh*P);
            P *= ph; E *= qh; w = nw;
        }
        for (int t = 3; t > sub; t--) {
            float ph = wfm[t*3+0], qh = wfm[t*3+1], gh = wfm[t*3+2];
            float nw = fmaf(qh, w, gh*P);
            P *= ph; E *= qh; w = nw;
        }
        #pragma unroll
        for (int s = LF-1; s >= 0; s--) {
            float4 g = sG[sub*LF + s];
            float th = g.z;
            sA[sub*LF + s] = -th * w;
            sB[sub*LF + s] = -th * E;
            P *= g.x;
            E *= g.y;
            w  = fmaf(g.y, w, P);
        }
    }

    // ---- A1: replay LF=16 steps from smem (q prefetched to regs) ----
    {
        float* __restrict__ op = d_out + (b*NS + t0f)*ND + i;
        float q16[LF];
        #pragma unroll
        for (int s = 0; s < LF; s++) q16[s] = qp[s*ND];
        #pragma unroll
        for (int st = 0; st < LF; st++) {
            const int row = sub*LF + st;
            float4 gg = sG[row];
            float  kk = Kraw[row*ND + i];
            float  vv = Eraw[row*ND + i];
            float om = gg.x, e = gg.y, th = gg.z;
            op[st*ND] = q16[st] * dm;
            float err = fmaf(kk, dm, -vv);
            Eraw[row*ND + i] = err;
            float t1 = th*kk, c2 = t1*vv, d0 = -t1*kk;
            float inner = fmaf(e, ds, c2);
            ds = fmaf(d0, dm, inner);
            dm = fmaf(om, dm, ds);
        }
    }
    __syncthreads();

    // ---- phase B: convert + weight + transpose (overlays ENT/fm) ----
    #pragma unroll
    for (int r = 0; r < 16; r++) {
        const int idx = tid + r*512;        // = s*ND + i2
        const int s = idx >> 7, i2 = idx & 127;
        const float kf = Kraw[idx];
        const float ef = Eraw[idx];
        const float pa = sA[s] * kf;
        const float pb = sB[s] * kf;
        __nv_bfloat16 h, l;
        bf16split(pa, h, l); KAh[i2*KP + s] = h; KAl[i2*KP + s] = l;
        bf16split(pb, h, l); KBh[i2*KP + s] = h; KBl[i2*KP + s] = l;
        bf16split(ef, h, l); ETh[i2*KP + s] = h; ETl[i2*KP + s] = l;
    }
    __syncthreads();

    // ---- phase C: tensor-core weighted outer products ----
    const int which = tid >> 8;
    const int t256 = tid & 255;
    const int lane = t256 & 31, warp = t256 >> 5;
    const int g = lane >> 2, tig = lane & 3;
    const int wm = warp >> 1, wn = warp & 1;
    const __nv_bfloat16* __restrict__ Ah = which ? KBh : KAh;
    const __nv_bfloat16* __restrict__ Al = which ? KBl : KAl;

    float acc[2][8][4];
    #pragma unroll
    for (int mt = 0; mt < 2; mt++)
        #pragma unroll
        for (int nt = 0; nt < 8; nt++)
            #pragma unroll
            for (int r = 0; r < 4; r++) acc[mt][nt][r] = 0.f;

    #pragma unroll
    for (int kk = 0; kk < LC; kk += 16) {
        unsigned ah[2][4], al[2][4];
        #pragma unroll
        for (int mt = 0; mt < 2; mt++) {
            const int r0 = (wm*32 + mt*16 + g)*KP + kk + tig*2;
            const int r1 = r0 + 8*KP;
            ah[mt][0] = *reinterpret_cast<const unsigned*>(&Ah[r0]);
            ah[mt][1] = *reinterpret_cast<const unsigned*>(&Ah[r1]);
            ah[mt][2] = *reinterpret_cast<const unsigned*>(&Ah[r0 + 8]);
            ah[mt][3] = *reinterpret_cast<const unsigned*>(&Ah[r1 + 8]);
            al[mt][0] = *reinterpret_cast<const unsigned*>(&Al[r0]);
            al[mt][1] = *reinterpret_cast<const unsigned*>(&Al[r1]);
            al[mt][2] = *reinterpret_cast<const unsigned*>(&Al[r0 + 8]);
            al[mt][3] = *reinterpret_cast<const unsigned*>(&Al[r1 + 8]);
        }
        #pragma unroll
        for (int nt = 0; nt < 8; nt++) {
            const int bo = (wn*64 + nt*8 + g)*KP + kk + tig*2;
            unsigned bh[2], bl[2];
            bh[0] = *reinterpret_cast<const unsigned*>(&ETh[bo]);
            bh[1] = *reinterpret_cast<const unsigned*>(&ETh[bo + 8]);
            bl[0] = *reinterpret_cast<const unsigned*>(&ETl[bo]);
            bl[1] = *reinterpret_cast<const unsigned*>(&ETl[bo + 8]);
            #pragma unroll
            for (int mt = 0; mt < 2; mt++) {
                mma16816(acc[mt][nt], ah[mt], bh);
                mma16816(acc[mt][nt], ah[mt], bl);
                mma16816(acc[mt][nt], al[mt], bh);
            }
        }
    }

    float* __restrict__ C = g_part + ((b*2 + which)*NC + c)*ND*ND;
    #pragma unroll
    for (int mt = 0; mt < 2; mt++) {
        const int r0 = wm*32 + mt*16 + g;
        const int r1 = r0 + 8;
        #pragma unroll
        for (int nt = 0; nt < 8; nt++) {
            const int c0 = wn*64 + nt*8 + tig*2;
            *reinterpret_cast<float2*>(&C[r0*ND + c0]) = make_float2(acc[mt][nt][0], acc[mt][nt][1]);
            *reinterpret_cast<float2*>(&C[r1*ND + c0]) = make_float2(acc[mt][nt][2], acc[mt][nt][3]);
        }
    }
}

// ============================================================
// Kernel 5: reduce split partials -> d_out tail
// asm volatile v4 loads: ptxas cannot reorder/sink them, forcing all 16
// loads in flight (MLP=16) before the adds consume results.
// ============================================================
__global__ __launch_bounds__(256) void reduce_kernel(float* __restrict__ d_out)
{
    const int g4 = blockIdx.x * 256 + threadIdx.x;   // [0, 65536) float4 units
    const int gid = g4 * 4;
    const int which = gid >> 17;
    const int r  = gid & 131071;
    const int b  = r >> 14;
    const int ij = r & 16383;
    const float* __restrict__ p = g_part + ((b*2 + which)*NC)*ND*ND + ij;

    float4 t[NC];
    #pragma unroll
    for (int sp = 0; sp < NC; sp++) {
        asm volatile("ld.global.v4.f32 {%0,%1,%2,%3}, [%4];"
            : "=f"(t[sp].x), "=f"(t[sp].y), "=f"(t[sp].z), "=f"(t[sp].w)
            : "l"(p + sp*ND*ND));
    }
    #pragma unroll
    for (int stride = 1; stride < NC; stride <<= 1)
        #pragma unroll
        for (int sp = 0; sp < NC; sp += stride*2) {
            t[sp].x += t[sp+stride].x; t[sp].y += t[sp+stride].y;
            t[sp].z += t[sp+stride].z; t[sp].w += t[sp+stride].w;
        }
    *reinterpret_cast<float4*>(&d_out[BSD + gid]) = t[0];
}

// ============================================================
extern "C" void kernel_launch(void* const* d_in, const int* in_sizes, int n_in,
                              void* d_out, int out_size)
{
    const float* x  = (const float*)d_in[0];
    const float* Wk = (const float*)d_in[1];
    const float* Wv = (const float*)d_in[2];
    const float* Wq = (const float*)d_in[3];
    const float* Wg = (const float*)d_in[4];
    const float* bg = (const float*)d_in[5];
    float* out = (float*)d_out;

    const int k1_smem = 4 * 128 * KP * (int)sizeof(__nv_bfloat16);  // 73728 B
    cudaFuncSetAttribute(k1_qkv_gates, cudaFuncAttributeMaxDynamicSharedMemorySize, k1_smem);
    cudaFuncSetAttribute(fused3_kernel, cudaFuncAttributeMaxDynamicSharedMemorySize, F3_SMEM);

    k1_qkv_gates<<<dim3(64, 4), 256, k1_smem>>>(x, Wk, Wv, Wq, Wg, bg);
    pass1_kernel<<<NB*NC + 1, 128>>>();
    fused3_kernel<<<NB*NC, 512, F3_SMEM>>>(out);
    reduce_kernel<<<256, 256>>>(out);
}

// round 14
// speedup vs baseline: 1.0535x; 1.0467x over previous
#include <cuda_runtime.h>
#include <cuda_bf16.h>
#include <stdint.h>

#define NB 8
#define NS 1024
#define ND 128
#define NROWS (NB*NS)   // 8192
#define BSD (NB*NS*ND)  // 1048576

#define NC 16           // coarse chunks (GEMM splits)
#define LC 64           // steps per coarse chunk
#define LF 16           // steps per fine sub-chunk (replay granularity)
#define UG 8            // prefetch group size (pass1)
#define NGRP (LC/UG)

#define KP 72           // padded bf16 k-stride in smem (conflict-free frag loads)

// ---- scratch (static device globals; no runtime allocation) ----
__device__ float  g_k[NROWS*ND];
__device__ float  g_v[NROWS*ND];
__device__ float  g_q[NROWS*ND];
__device__ float4 g_g4[NROWS];           // (om=1-a, e, th, 0) per (b,t)
__device__ float  g_dmap[6*NB*NC*ND];    // composed coarse diag maps
__device__ float  g_wmap[3*NB*NC];
__device__ float  g_part[NB*2*NC*ND*ND];

// ---- mma.sync m16n8k16 bf16 -> f32 ----
__device__ __forceinline__ void mma16816(float* c, const unsigned* a, const unsigned* b)
{
    asm volatile(
        "mma.sync.aligned.m16n8k16.row.col.f32.bf16.bf16.f32 "
        "{%0,%1,%2,%3}, {%4,%5,%6,%7}, {%8,%9}, {%0,%1,%2,%3};"
        : "+f"(c[0]), "+f"(c[1]), "+f"(c[2]), "+f"(c[3])
        : "r"(a[0]), "r"(a[1]), "r"(a[2]), "r"(a[3]), "r"(b[0]), "r"(b[1]));
}

__device__ __forceinline__ void bf16split(float f, __nv_bfloat16& h, __nv_bfloat16& l)
{
    h = __float2bfloat16_rn(f);
    l = __float2bfloat16_rn(f - __bfloat162float(h));
}

// packed split of two floats -> (hi pair, lo pair)
__device__ __forceinline__ void bf16split2(float a, float b,
                                           __nv_bfloat162& hp, __nv_bfloat162& lp)
{
    hp = __floats2bfloat162_rn(a, b);
    float ra = a - __bfloat162float(__low2bfloat16(hp));
    float rb = b - __bfloat162float(__high2bfloat16(hp));
    lp = __floats2bfloat162_rn(ra, rb);
}

// ============================================================
// Kernel 1: y<3: k/v/q = x@W via bf16-split tensor mma; y==3: gates
// ============================================================
__global__ __launch_bounds__(256) void k1_qkv_gates(
    const float* __restrict__ x, const float* __restrict__ Wk,
    const float* __restrict__ Wv, const float* __restrict__ Wq,
    const float* __restrict__ Wg, const float* __restrict__ bg)
{
    const int which = blockIdx.y;
    if (which == 3) {
        const int base = blockIdx.x * 128;
        const int w = threadIdx.x >> 5, lane = threadIdx.x & 31;
        const float b0 = bg[0], b1 = bg[1], b2 = bg[2];
        const float w0a = Wg[lane*3+0],      w0b = Wg[lane*3+1],      w0c = Wg[lane*3+2];
        const float w1a = Wg[(lane+32)*3+0], w1b = Wg[(lane+32)*3+1], w1c = Wg[(lane+32)*3+2];
        const float w2a = Wg[(lane+64)*3+0], w2b = Wg[(lane+64)*3+1], w2c = Wg[(lane+64)*3+2];
        const float w3a = Wg[(lane+96)*3+0], w3b = Wg[(lane+96)*3+1], w3c = Wg[(lane+96)*3+2];
        for (int rr = 0; rr < 16; rr++) {
            const int r = base + w*16 + rr;
            const float* __restrict__ xr = x + r * ND;
            float x0 = xr[lane], x1 = xr[lane+32], x2 = xr[lane+64], x3 = xr[lane+96];
            float s0 = x0*w0a + x1*w1a + x2*w2a + x3*w3a;
            float s1 = x0*w0b + x1*w1b + x2*w2b + x3*w3b;
            float s2 = x0*w0c + x1*w1c + x2*w2c + x3*w3c;
            #pragma unroll
            for (int o = 16; o; o >>= 1) {
                s0 += __shfl_xor_sync(0xffffffffu, s0, o);
                s1 += __shfl_xor_sync(0xffffffffu, s1, o);
                s2 += __shfl_xor_sync(0xffffffffu, s2, o);
            }
            if (lane == 0) {
                float om = 1.f / (1.f + expf(s0 + b0));       // 1 - sigmoid
                float e  = 1.f / (1.f + expf(-(s1 + b1)));
                float th = 1.f / (1.f + expf(-(s2 + b2)));
                g_g4[r] = make_float4(om, e, th, 0.f);
            }
        }
        return;
    }
    extern __shared__ __nv_bfloat16 bsm[];
    __nv_bfloat16* __restrict__ XH  = bsm;
    __nv_bfloat16* __restrict__ XL  = XH  + 128*KP;
    __nv_bfloat16* __restrict__ WTH = XL  + 128*KP;
    __nv_bfloat16* __restrict__ WTL = WTH + 128*KP;

    const float* __restrict__ W = (which == 0) ? Wk : ((which == 1) ? Wv : Wq);
    float* __restrict__ out = (which == 0) ? g_k : ((which == 1) ? g_v : g_q);
    const int rowBase = blockIdx.x * 128;

    const int tid  = threadIdx.x;
    const int lane = tid & 31;
    const int warp = tid >> 5;
    const int g    = lane >> 2;
    const int tig  = lane & 3;
    const int wm   = warp >> 1;
    const int wn   = warp & 1;

    float acc[2][8][4];
    #pragma unroll
    for (int mt = 0; mt < 2; mt++)
        #pragma unroll
        for (int nt = 0; nt < 8; nt++)
            #pragma unroll
            for (int r = 0; r < 4; r++) acc[mt][nt][r] = 0.f;

    for (int k0 = 0; k0 < 128; k0 += 64) {
        {
            const int row = tid >> 1, half = tid & 1;
            const float* __restrict__ src = x + (rowBase + row)*ND + k0 + half*32;
            __nv_bfloat16* __restrict__ dh = XH + row*KP + half*32;
            __nv_bfloat16* __restrict__ dl = XL + row*KP + half*32;
            #pragma unroll
            for (int j = 0; j < 8; j++) {
                float4 v = *reinterpret_cast<const float4*>(&src[j*4]);
                __nv_bfloat162 hp, lp;
                bf16split2(v.x, v.y, hp, lp);
                *reinterpret_cast<__nv_bfloat162*>(&dh[j*4])   = hp;
                *reinterpret_cast<__nv_bfloat162*>(&dl[j*4])   = lp;
                bf16split2(v.z, v.w, hp, lp);
                *reinterpret_cast<__nv_bfloat162*>(&dh[j*4+2]) = hp;
                *reinterpret_cast<__nv_bfloat162*>(&dl[j*4+2]) = lp;
            }
        }
        {
            const int krow = tid >> 2, nb = (tid & 3)*32;
            const float* __restrict__ src = W + (k0 + krow)*ND + nb;
            #pragma unroll
            for (int j = 0; j < 8; j++) {
                float4 v = *reinterpret_cast<const float4*>(&src[j*4]);
                #pragma unroll
                for (int i = 0; i < 4; i++) {
                    __nv_bfloat16 h, l;
                    bf16split((&v.x)[i], h, l);
                    const int n = nb + j*4 + i;
                    WTH[n*KP + krow] = h;
                    WTL[n*KP + krow] = l;
                }
            }
        }
        __syncthreads();

        #pragma unroll
        for (int kk = 0; kk < 64; kk += 16) {
            unsigned ah[2][4], al[2][4];
            #pragma unroll
            for (int mt = 0; mt < 2; mt++) {
                const int r0 = (wm*32 + mt*16 + g)*KP + kk + tig*2;
                const int r1 = r0 + 8*KP;
                ah[mt][0] = *reinterpret_cast<const unsigned*>(&XH[r0]);
                ah[mt][1] = *reinterpret_cast<const unsigned*>(&XH[r1]);
                ah[mt][2] = *reinterpret_cast<const unsigned*>(&XH[r0 + 8]);
                ah[mt][3] = *reinterpret_cast<const unsigned*>(&XH[r1 + 8]);
                al[mt][0] = *reinterpret_cast<const unsigned*>(&XL[r0]);
                al[mt][1] = *reinterpret_cast<const unsigned*>(&XL[r1]);
                al[mt][2] = *reinterpret_cast<const unsigned*>(&XL[r0 + 8]);
                al[mt][3] = *reinterpret_cast<const unsigned*>(&XL[r1 + 8]);
            }
            #pragma unroll
            for (int nt = 0; nt < 8; nt++) {
                const int bo = (wn*64 + nt*8 + g)*KP + kk + tig*2;
                unsigned bh[2], bl[2];
                bh[0] = *reinterpret_cast<const unsigned*>(&WTH[bo]);
                bh[1] = *reinterpret_cast<const unsigned*>(&WTH[bo + 8]);
                bl[0] = *reinterpret_cast<const unsigned*>(&WTL[bo]);
                bl[1] = *reinterpret_cast<const unsigned*>(&WTL[bo + 8]);
                #pragma unroll
                for (int mt = 0; mt < 2; mt++) {
                    mma16816(acc[mt][nt], ah[mt], bh);
                    mma16816(acc[mt][nt], ah[mt], bl);
                    mma16816(acc[mt][nt], al[mt], bh);
                }
            }
        }
        __syncthreads();
    }

    #pragma unroll
    for (int mt = 0; mt < 2; mt++) {
        const int r0 = rowBase + wm*32 + mt*16 + g;
        const int r1 = r0 + 8;
        #pragma unroll
        for (int nt = 0; nt < 8; nt++) {
            const int c0 = wn*64 + nt*8 + tig*2;
            *reinterpret_cast<float2*>(&out[r0*ND + c0]) = make_float2(acc[mt][nt][0], acc[mt][nt][1]);
            *reinterpret_cast<float2*>(&out[r1*ND + c0]) = make_float2(acc[mt][nt][2], acc[mt][nt][3]);
        }
    }
}

// ============================================================
// Pass 1: coarse chunk map composition (diag maps + weight maps)
// ============================================================
__global__ __launch_bounds__(128) void pass1_kernel()
{
    const int blk = blockIdx.x;
    if (blk < NB*NC) {
        const int b = blk >> 4, c = blk & (NC-1);
        const int i = threadIdx.x;
        const int t0 = c * LC;
        const float*  __restrict__ kp = g_k + (b*NS + t0)*ND + i;
        const float*  __restrict__ vp = g_v + (b*NS + t0)*ND + i;
        const float4* __restrict__ gp = g_g4 + b*NS + t0;

        float m00=1.f, m01=0.f, m10=0.f, m11=1.f, w0=0.f, w1=0.f;
        float kA[UG], vA[UG], kB[UG], vB[UG];
        float4 gA[UG], gB[UG];
        #pragma unroll
        for (int s = 0; s < UG; s++) { kA[s]=kp[s*ND]; vA[s]=vp[s*ND]; gA[s]=gp[s]; }

        #pragma unroll
        for (int g = 0; g < NGRP; g++) {
            const bool useA = ((g & 1) == 0);
            if (g + 1 < NGRP) {
                #pragma unroll
                for (int s = 0; s < UG; s++) {
                    int off = ((g+1)*UG + s)*ND;
                    int go  = (g+1)*UG + s;
                    if (useA) { kB[s]=kp[off]; vB[s]=vp[off]; gB[s]=gp[go]; }
                    else      { kA[s]=kp[off]; vA[s]=vp[off]; gA[s]=gp[go]; }
                }
            }
            #pragma unroll
            for (int s = 0; s < UG; s++) {
                float  kk = useA ? kA[s] : kB[s];
                float  vv = useA ? vA[s] : vB[s];
                float4 gg = useA ? gA[s] : gB[s];
                float om = gg.x, e = gg.y, th = gg.z;
                float t1 = th*kk, c2 = t1*vv, d0 = -t1*kk, a00 = om + d0;
                float te0 = e*m10, te1 = e*m11;
                float n00 = fmaf(a00, m00, te0), n10 = fmaf(d0, m00, te0);
                float n01 = fmaf(a00, m01, te1), n11 = fmaf(d0, m01, te1);
                float tev = fmaf(e, w1, c2);
                float nw0 = fmaf(a00, w0, tev), nw1 = fmaf(d0, w0, tev);
                m00=n00; m01=n01; m10=n10; m11=n11; w0=nw0; w1=nw1;
            }
        }
        const int base = (b*NC + c)*ND + i;
        const int ST = NB*NC*ND;
        g_dmap[0*ST+base] = m00; g_dmap[1*ST+base] = m01;
        g_dmap[2*ST+base] = m10; g_dmap[3*ST+base] = m11;
        g_dmap[4*ST+base] = w0;  g_dmap[5*ST+base] = w1;
    } else {
        const int u = threadIdx.x;
        const int b = u >> 4, wc = u & (NC-1);
        const float4* __restrict__ gp = g_g4 + b*NS + wc*LC;
        float ph = 1.f, qh = 1.f, gh = 0.f;
        #pragma unroll 4
        for (int s = LC-1; s >= 0; s--) {
            float4 g = gp[s];
            float p = g.x, q = g.y;
            gh = fmaf(q, gh, p*ph);
            ph *= p;
            qh *= q;
        }
        g_wmap[0*NB*NC + u] = ph;
        g_wmap[1*NB*NC + u] = qh;
        g_wmap[2*NB*NC + u] = gh;
    }
}

// ============================================================
// Fused pass 3 (pass2 inlined): per (b, coarse chunk) block, 512 threads
// [exact R8 structure]
// ============================================================
#define F3_ENT_OFF   65536
#define F3_FM_OFF    (65536 + 49152)
#define F3_SG_OFF    176128
#define F3_SA_OFF    177152
#define F3_WENT_OFF  177664
#define F3_SMEM      177920

__global__ __launch_bounds__(512) void fused3_kernel(float* __restrict__ d_out)
{
    extern __shared__ char smc[];
    float* __restrict__ Kraw = reinterpret_cast<float*>(smc);            // [64][128]
    float* __restrict__ Eraw = Kraw + LC*ND;                             // [64][128]
    float* __restrict__ ENT  = reinterpret_cast<float*>(smc + F3_ENT_OFF);  // [6][16][128]
    float* __restrict__ fm   = reinterpret_cast<float*>(smc + F3_FM_OFF);   // [6][4][128]
    float4* __restrict__ sG  = reinterpret_cast<float4*>(smc + F3_SG_OFF);  // [64]
    float* __restrict__ sA   = reinterpret_cast<float*>(smc + F3_SA_OFF);   // [64]
    float* __restrict__ sB   = sA + LC;                                  // [64]
    float* __restrict__ wENT = reinterpret_cast<float*>(smc + F3_WENT_OFF); // [16][3]
    float* __restrict__ wfm  = wENT + 48;                                // [4][3]
    __nv_bfloat16* __restrict__ KAh = reinterpret_cast<__nv_bfloat16*>(smc + F3_ENT_OFF);
    __nv_bfloat16* __restrict__ KAl = KAh + ND*KP;
    __nv_bfloat16* __restrict__ KBh = KAl + ND*KP;
    __nv_bfloat16* __restrict__ KBl = KBh + ND*KP;
    __nv_bfloat16* __restrict__ ETh = KBl + ND*KP;
    __nv_bfloat16* __restrict__ ETl = ETh + ND*KP;

    const int b = blockIdx.x >> 4, c = blockIdx.x & (NC-1);
    const int tid = threadIdx.x;
    const int sub = tid >> 7, i = tid & 127;
    const int t0f = c*LC + sub*LF;
    const float*  __restrict__ kp = g_k + (b*NS + t0f)*ND + i;
    const float*  __restrict__ vp = g_v + (b*NS + t0f)*ND + i;
    const float*  __restrict__ qp = g_q + (b*NS + t0f)*ND + i;
    const float4* __restrict__ gp = g_g4 + b*NS + t0f;

    // ---- cooperative prefetch of coarse maps (entry-state inputs) ----
    {
        const int ST = NB*NC*ND;
        const int nEl = c * 128;
        #pragma unroll
        for (int jj = 0; jj < 6; jj++)
            for (int u = tid; u < nEl; u += 512)
                ENT[jj*2048 + u] = g_dmap[jj*ST + b*NC*ND + u];
        if (tid < 48) {
            const int t = tid / 3, j = tid % 3;
            wENT[t*3 + j] = g_wmap[j*NB*NC + b*NC + t];
        }
    }
    // gates -> smem (per sub, 16 threads)
    if (i < LF) sG[sub*LF + i] = gp[i];

    // ---- A0: compose fine diag map over LF=16 steps; stage k/v to smem ----
    {
        float m00=1.f, m01=0.f, m10=0.f, m11=1.f, w0=0.f, w1=0.f;
        float kA[4], vA[4], kB[4], vB[4];
        float4 gA[4], gB[4];
        #pragma unroll
        for (int s = 0; s < 4; s++) { kA[s]=kp[s*ND]; vA[s]=vp[s*ND]; gA[s]=gp[s]; }
        #pragma unroll
        for (int g = 0; g < 4; g++) {
            const bool useA = ((g & 1) == 0);
            if (g < 3) {
                #pragma unroll
                for (int s = 0; s < 4; s++) {
                    int off = ((g+1)*4 + s)*ND, go = (g+1)*4 + s;
                    if (useA) { kB[s]=kp[off]; vB[s]=vp[off]; gB[s]=gp[go]; }
                    else      { kA[s]=kp[off]; vA[s]=vp[off]; gA[s]=gp[go]; }
                }
            }
            #pragma unroll
            for (int s = 0; s < 4; s++) {
                float  kk = useA ? kA[s] : kB[s];
                float  vv = useA ? vA[s] : vB[s];
                float4 gg = useA ? gA[s] : gB[s];
                const int row = sub*LF + g*4 + s;
                Kraw[row*ND + i] = kk;
                Eraw[row*ND + i] = vv;
                float om = gg.x, e = gg.y, th = gg.z;
                float t1 = th*kk, c2 = t1*vv, d0 = -t1*kk, a00 = om + d0;
                float te0 = e*m10, te1 = e*m11;
                float n00 = fmaf(a00, m00, te0), n10 = fmaf(d0, m00, te0);
                float n01 = fmaf(a00, m01, te1), n11 = fmaf(d0, m01, te1);
                float tev = fmaf(e, w1, c2);
                float nw0 = fmaf(a00, w0, tev), nw1 = fmaf(d0, w0, tev);
                m00=n00; m01=n01; m10=n10; m11=n11; w0=nw0; w1=nw1;
            }
        }
        fm[(0*4+sub)*128+i] = m00; fm[(1*4+sub)*128+i] = m01;
        fm[(2*4+sub)*128+i] = m10; fm[(3*4+sub)*128+i] = m11;
        fm[(4*4+sub)*128+i] = w0;  fm[(5*4+sub)*128+i] = w1;
    }
    if (i == 0) {
        float ph = 1.f, qh = 1.f, gh = 0.f;
        #pragma unroll
        for (int s = LF-1; s >= 0; s--) {
            float4 g = gp[s];
            gh = fmaf(g.y, gh, g.x*ph);
            ph *= g.x;
            qh *= g.y;
        }
        wfm[sub*3+0] = ph; wfm[sub*3+1] = qh; wfm[sub*3+2] = gh;
    }
    __syncthreads();

    // ---- combine: coarse entry (over chunks t<c) then fine maps (t<sub) ----
    float dm = 0.f, ds = 0.f;
    for (int t = 0; t < c; t++) {
        float a00 = ENT[0*2048 + t*128 + i], a01 = ENT[1*2048 + t*128 + i];
        float a10 = ENT[2*2048 + t*128 + i], a11 = ENT[3*2048 + t*128 + i];
        float v0  = ENT[4*2048 + t*128 + i], v1  = ENT[5*2048 + t*128 + i];
        float n0 = fmaf(a00, dm, fmaf(a01, ds, v0));
        float n1 = fmaf(a10, dm, fmaf(a11, ds, v1));
        dm = n0; ds = n1;
    }
    for (int t = 0; t < sub; t++) {
        float a00 = fm[(0*4+t)*128+i], a01 = fm[(1*4+t)*128+i];
        float a10 = fm[(2*4+t)*128+i], a11 = fm[(3*4+t)*128+i];
        float v0  = fm[(4*4+t)*128+i], v1  = fm[(5*4+t)*128+i];
        float n0 = fmaf(a00, dm, fmaf(a01, ds, v0));
        float n1 = fmaf(a10, dm, fmaf(a11, ds, v1));
        dm = n0; ds = n1;
    }

    if (i == 0) {
        float P = 1.f, E = 1.f, w = 1.f;
        for (int t = NC-1; t > c; t--) {
            float ph = wENT[t*3+0], qh = wENT[t*3+1], gh = wENT[t*3+2];
            float nw = fmaf(qh, w, gh*P);
            P *= ph; E *= qh; w = nw;
        }
        for (int t = 3; t > sub; t--) {
            float ph = wfm[t*3+0], qh = wfm[t*3+1], gh = wfm[t*3+2];
            float nw = fmaf(qh, w, gh*P);
            P *= ph; E *= qh; w = nw;
        }
        #pragma unroll
        for (int s = LF-1; s >= 0; s--) {
            float4 g = sG[sub*LF + s];
            float th = g.z;
            sA[sub*LF + s] = -th * w;
            sB[sub*LF + s] = -th * E;
            P *= g.x;
            E *= g.y;
            w  = fmaf(g.y, w, P);
        }
    }

    // ---- A1: replay LF=16 steps from smem (q prefetched to regs) ----
    {
        float* __restrict__ op = d_out + (b*NS + t0f)*ND + i;
        float q16[LF];
        #pragma unroll
        for (int s = 0; s < LF; s++) q16[s] = qp[s*ND];
        #pragma unroll
        for (int st = 0; st < LF; st++) {
            const int row = sub*LF + st;
            float4 gg = sG[row];
            float  kk = Kraw[row*ND + i];
            float  vv = Eraw[row*ND + i];
            float om = gg.x, e = gg.y, th = gg.z;
            op[st*ND] = q16[st] * dm;
            float err = fmaf(kk, dm, -vv);
            Eraw[row*ND + i] = err;
            float t1 = th*kk, c2 = t1*vv, d0 = -t1*kk;
            float inner = fmaf(e, ds, c2);
            ds = fmaf(d0, dm, inner);
            dm = fmaf(om, dm, ds);
        }
    }
    __syncthreads();

    // ---- phase B: convert + weight + transpose (overlays ENT/fm) ----
    #pragma unroll
    for (int r = 0; r < 16; r++) {
        const int idx = tid + r*512;        // = s*ND + i2
        const int s = idx >> 7, i2 = idx & 127;
        const float kf = Kraw[idx];
        const float ef = Eraw[idx];
        const float pa = sA[s] * kf;
        const float pb = sB[s] * kf;
        __nv_bfloat16 h, l;
        bf16split(pa, h, l); KAh[i2*KP + s] = h; KAl[i2*KP + s] = l;
        bf16split(pb, h, l); KBh[i2*KP + s] = h; KBl[i2*KP + s] = l;
        bf16split(ef, h, l); ETh[i2*KP + s] = h; ETl[i2*KP + s] = l;
    }
    __syncthreads();

    // ---- phase C: tensor-core weighted outer products ----
    const int which = tid >> 8;
    const int t256 = tid & 255;
    const int lane = t256 & 31, warp = t256 >> 5;
    const int g = lane >> 2, tig = lane & 3;
    const int wm = warp >> 1, wn = warp & 1;
    const __nv_bfloat16* __restrict__ Ah = which ? KBh : KAh;
    const __nv_bfloat16* __restrict__ Al = which ? KBl : KAl;

    float acc[2][8][4];
    #pragma unroll
    for (int mt = 0; mt < 2; mt++)
        #pragma unroll
        for (int nt = 0; nt < 8; nt++)
            #pragma unroll
            for (int r = 0; r < 4; r++) acc[mt][nt][r] = 0.f;

    #pragma unroll
    for (int kk = 0; kk < LC; kk += 16) {
        unsigned ah[2][4], al[2][4];
        #pragma unroll
        for (int mt = 0; mt < 2; mt++) {
            const int r0 = (wm*32 + mt*16 + g)*KP + kk + tig*2;
            const int r1 = r0 + 8*KP;
            ah[mt][0] = *reinterpret_cast<const unsigned*>(&Ah[r0]);
            ah[mt][1] = *reinterpret_cast<const unsigned*>(&Ah[r1]);
            ah[mt][2] = *reinterpret_cast<const unsigned*>(&Ah[r0 + 8]);
            ah[mt][3] = *reinterpret_cast<const unsigned*>(&Ah[r1 + 8]);
            al[mt][0] = *reinterpret_cast<const unsigned*>(&Al[r0]);
            al[mt][1] = *reinterpret_cast<const unsigned*>(&Al[r1]);
            al[mt][2] = *reinterpret_cast<const unsigned*>(&Al[r0 + 8]);
            al[mt][3] = *reinterpret_cast<const unsigned*>(&Al[r1 + 8]);
        }
        #pragma unroll
        for (int nt = 0; nt < 8; nt++) {
            const int bo = (wn*64 + nt*8 + g)*KP + kk + tig*2;
            unsigned bh[2], bl[2];
            bh[0] = *reinterpret_cast<const unsigned*>(&ETh[bo]);
            bh[1] = *reinterpret_cast<const unsigned*>(&ETh[bo + 8]);
            bl[0] = *reinterpret_cast<const unsigned*>(&ETl[bo]);
            bl[1] = *reinterpret_cast<const unsigned*>(&ETl[bo + 8]);
            #pragma unroll
            for (int mt = 0; mt < 2; mt++) {
                mma16816(acc[mt][nt], ah[mt], bh);
                mma16816(acc[mt][nt], ah[mt], bl);
                mma16816(acc[mt][nt], al[mt], bh);
            }
        }
    }

    float* __restrict__ C = g_part + ((b*2 + which)*NC + c)*ND*ND;
    #pragma unroll
    for (int mt = 0; mt < 2; mt++) {
        const int r0 = wm*32 + mt*16 + g;
        const int r1 = r0 + 8;
        #pragma unroll
        for (int nt = 0; nt < 8; nt++) {
            const int c0 = wn*64 + nt*8 + tig*2;
            *reinterpret_cast<float2*>(&C[r0*ND + c0]) = make_float2(acc[mt][nt][0], acc[mt][nt][1]);
            *reinterpret_cast<float2*>(&C[r1*ND + c0]) = make_float2(acc[mt][nt][2], acc[mt][nt][3]);
        }
    }
}

// ============================================================
// Kernel 5: reduce split partials -> d_out tail (float4) [R8 form]
// ============================================================
__global__ __launch_bounds__(256) void reduce_kernel(float* __restrict__ d_out)
{
    const int g4 = blockIdx.x * 256 + threadIdx.x;   // [0, 65536) float4 units
    const int gid = g4 * 4;
    const int which = gid >> 17;
    const int r  = gid & 131071;
    const int b  = r >> 14;
    const int ij = r & 16383;
    const float* __restrict__ p = g_part + ((b*2 + which)*NC)*ND*ND + ij;
    float4 s = make_float4(0.f, 0.f, 0.f, 0.f);
    #pragma unroll
    for (int sp = 0; sp < NC; sp++) {
        float4 v = *reinterpret_cast<const float4*>(&p[sp*ND*ND]);
        s.x += v.x; s.y += v.y; s.z += v.z; s.w += v.w;
    }
    *reinterpret_cast<float4*>(&d_out[BSD + gid]) = s;
}

// ============================================================
extern "C" void kernel_launch(void* const* d_in, const int* in_sizes, int n_in,
                              void* d_out, int out_size)
{
    const float* x  = (const float*)d_in[0];
    const float* Wk = (const float*)d_in[1];
    const float* Wv = (const float*)d_in[2];
    const float* Wq = (const float*)d_in[3];
    const float* Wg = (const float*)d_in[4];
    const float* bg = (const float*)d_in[5];
    float* out = (float*)d_out;

    const int k1_smem = 4 * 128 * KP * (int)sizeof(__nv_bfloat16);  // 73728 B
    cudaFuncSetAttribute(k1_qkv_gates, cudaFuncAttributeMaxDynamicSharedMemorySize, k1_smem);
    cudaFuncSetAttribute(fused3_kernel, cudaFuncAttributeMaxDynamicSharedMemorySize, F3_SMEM);

    k1_qkv_gates<<<dim3(64, 4), 256, k1_smem>>>(x, Wk, Wv, Wq, Wg, bg);
    pass1_kernel<<<NB*NC + 1, 128>>>();
    fused3_kernel<<<NB*NC, 512, F3_SMEM>>>(out);
    reduce_kernel<<<256, 256>>>(out);
}